// round 1
// baseline (speedup 1.0000x reference)
#include <cuda_runtime.h>
#include <cstdint>
#include <cstddef>

// Problem constants
#define B_   4
#define S_   2048
#define DM_  2048
#define HQ_  16
#define DH_  128
#define EQ_  3072      // (H_Q + 2*H_KV) * D_HEAD
#define MROWS_ 8192    // B*S

// Scratch (allocation-free rule: __device__ globals)
__device__ float g_qkv[(size_t)B_ * S_ * EQ_];   // 96 MB: fused QKV output
__device__ float g_att[(size_t)B_ * S_ * DM_];   // 64 MB: attention output

// ---------------------------------------------------------------------------
// GEMM: C[M,N] = A[M,K] * B[N,K]^T   (both operands row-major, K contiguous)
// 128x128 tile, BK=16, 256 threads, 8x8 fragment per thread, fp32.
// ---------------------------------------------------------------------------
__global__ void __launch_bounds__(256) gemm_nt(
    const float* __restrict__ A, const float* __restrict__ Bm,
    float* __restrict__ C, int M, int N, int K)
{
    __shared__ float As[16][132];   // [k][m], stride 132 to dodge store conflicts
    __shared__ float Bs[16][132];   // [k][n]

    const int tid = threadIdx.x;
    const int ty = tid >> 4;        // 0..15 -> 8 C-rows each
    const int tx = tid & 15;        // 0..15 -> 8 C-cols each
    const int m0 = blockIdx.y << 7;
    const int n0 = blockIdx.x << 7;

    const float* Ab = A + (size_t)m0 * K;
    const float* Bb = Bm + (size_t)n0 * K;

    float acc[8][8];
    #pragma unroll
    for (int i = 0; i < 8; ++i)
        #pragma unroll
        for (int j = 0; j < 8; ++j) acc[i][j] = 0.0f;

    const int lrow = tid >> 2;   // 0..63 (+64 on 2nd iter)
    const int lkv  = tid & 3;    // which float4 along k

    for (int k0 = 0; k0 < K; k0 += 16) {
        #pragma unroll
        for (int it = 0; it < 2; ++it) {
            const int row = lrow + it * 64;
            float4 a = *(const float4*)(Ab + (size_t)row * K + k0 + lkv * 4);
            float4 b = *(const float4*)(Bb + (size_t)row * K + k0 + lkv * 4);
            As[lkv*4+0][row] = a.x; As[lkv*4+1][row] = a.y;
            As[lkv*4+2][row] = a.z; As[lkv*4+3][row] = a.w;
            Bs[lkv*4+0][row] = b.x; Bs[lkv*4+1][row] = b.y;
            Bs[lkv*4+2][row] = b.z; Bs[lkv*4+3][row] = b.w;
        }
        __syncthreads();
        #pragma unroll
        for (int kk = 0; kk < 16; ++kk) {
            float4 a0 = *(const float4*)&As[kk][ty * 8];
            float4 a1 = *(const float4*)&As[kk][ty * 8 + 4];
            float4 b0 = *(const float4*)&Bs[kk][tx * 8];
            float4 b1 = *(const float4*)&Bs[kk][tx * 8 + 4];
            float av[8] = {a0.x, a0.y, a0.z, a0.w, a1.x, a1.y, a1.z, a1.w};
            float bv[8] = {b0.x, b0.y, b0.z, b0.w, b1.x, b1.y, b1.z, b1.w};
            #pragma unroll
            for (int i = 0; i < 8; ++i)
                #pragma unroll
                for (int j = 0; j < 8; ++j)
                    acc[i][j] += av[i] * bv[j];
        }
        __syncthreads();
    }

    #pragma unroll
    for (int i = 0; i < 8; ++i) {
        float* Crow = C + (size_t)(m0 + ty * 8 + i) * N + n0 + tx * 8;
        *(float4*)(Crow)     = make_float4(acc[i][0], acc[i][1], acc[i][2], acc[i][3]);
        *(float4*)(Crow + 4) = make_float4(acc[i][4], acc[i][5], acc[i][6], acc[i][7]);
    }
}

// ---------------------------------------------------------------------------
// Flash attention, fp32, GQA (kv head = h/4), additive mask.
// Tile: BQ=128 q-rows x BKV=128 keys, D=128. 256 threads, 8x8 fragments.
// smem: Qs[128][128] | KVs[128][128] (K swizzled, then V plain) | Ps[128][128]
// = 192 KB dynamic. One CTA per SM.
// ---------------------------------------------------------------------------
#define FLASH_SMEM (3 * 128 * 128 * 4)

__global__ void __launch_bounds__(256, 1) flash_attn(
    const float* __restrict__ qkv, const float* __restrict__ mask,
    float* __restrict__ outp)
{
    extern __shared__ float sm[];
    float4* Qs4  = (float4*)sm;                    // [row][32 f4]
    float4* KVs4 = (float4*)(sm + 128 * 128);      // [row][32 f4]
    float*  Ps   = sm + 2 * 128 * 128;             // [q][128]

    const int tid = threadIdx.x;
    const int ty  = tid >> 4;    // 0..15 -> q rows ty*8..+7
    const int tx  = tid & 15;    // 0..15 -> k cols / d cols tx*8..+7
    const int q0  = blockIdx.x << 7;
    const int h   = blockIdx.y;
    const int b   = blockIdx.z;
    const int kh  = h >> 2;                         // GQA: repeat_interleave(4)
    const size_t bS   = (size_t)b * S_;
    const size_t qoff = (size_t)h * DH_;
    const size_t koff = 2048 + (size_t)kh * DH_;
    const size_t voff = 2560 + (size_t)kh * DH_;
    const float scale = 0.08838834764831845f;       // 1/sqrt(128)

    // Load + pre-scale Q tile
    #pragma unroll
    for (int it = 0; it < 16; ++it) {
        const int idx = it * 256 + tid;
        const int row = idx >> 5, dv = idx & 31;
        float4 q = *(const float4*)(qkv + (bS + q0 + row) * EQ_ + qoff + dv * 4);
        q.x *= scale; q.y *= scale; q.z *= scale; q.w *= scale;
        Qs4[row * 32 + dv] = q;
    }

    float o[8][8];
    #pragma unroll
    for (int i = 0; i < 8; ++i)
        #pragma unroll
        for (int j = 0; j < 8; ++j) o[i][j] = 0.0f;
    float mrow[8], lrow[8];
    #pragma unroll
    for (int i = 0; i < 8; ++i) { mrow[i] = -3.0e38f; lrow[i] = 0.0f; }

    for (int k0 = 0; k0 < S_; k0 += 128) {
        __syncthreads();   // Q visible (iter 0); KVs free of prior P*V readers
        // Load K tile, XOR-swizzled so 8 consecutive rows hit distinct banks
        #pragma unroll
        for (int it = 0; it < 16; ++it) {
            const int idx = it * 256 + tid;
            const int row = idx >> 5, dv = idx & 31;
            float4 kf = *(const float4*)(qkv + (bS + k0 + row) * EQ_ + koff + dv * 4);
            KVs4[row * 32 + (dv ^ (row & 7))] = kf;
        }
        __syncthreads();

        // S = Q*K^T (Q pre-scaled)
        float s[8][8];
        #pragma unroll
        for (int i = 0; i < 8; ++i)
            #pragma unroll
            for (int j = 0; j < 8; ++j) s[i][j] = 0.0f;

        for (int dv = 0; dv < 32; ++dv) {
            float4 kf[8];
            #pragma unroll
            for (int j = 0; j < 8; ++j) {
                const int kc = tx * 8 + j;
                kf[j] = KVs4[kc * 32 + (dv ^ (kc & 7))];
            }
            #pragma unroll
            for (int i = 0; i < 8; ++i) {
                const float4 qf = Qs4[(ty * 8 + i) * 32 + dv];
                #pragma unroll
                for (int j = 0; j < 8; ++j) {
                    s[i][j] += qf.x * kf[j].x + qf.y * kf[j].y
                             + qf.z * kf[j].z + qf.w * kf[j].w;
                }
            }
        }

        // + additive mask, then online softmax
        #pragma unroll
        for (int i = 0; i < 8; ++i) {
            const float* mp = mask + (size_t)(q0 + ty * 8 + i) * S_ + k0 + tx * 8;
            const float4 m0v = *(const float4*)(mp);
            const float4 m1v = *(const float4*)(mp + 4);
            s[i][0] += m0v.x; s[i][1] += m0v.y; s[i][2] += m0v.z; s[i][3] += m0v.w;
            s[i][4] += m1v.x; s[i][5] += m1v.y; s[i][6] += m1v.z; s[i][7] += m1v.w;
        }

        #pragma unroll
        for (int i = 0; i < 8; ++i) {
            float rm = s[i][0];
            #pragma unroll
            for (int j = 1; j < 8; ++j) rm = fmaxf(rm, s[i][j]);
            rm = fmaxf(rm, __shfl_xor_sync(0xffffffffu, rm, 1));
            rm = fmaxf(rm, __shfl_xor_sync(0xffffffffu, rm, 2));
            rm = fmaxf(rm, __shfl_xor_sync(0xffffffffu, rm, 4));
            rm = fmaxf(rm, __shfl_xor_sync(0xffffffffu, rm, 8));
            const float mn   = fmaxf(mrow[i], rm);
            const float corr = __expf(mrow[i] - mn);
            float rs = 0.0f;
            #pragma unroll
            for (int j = 0; j < 8; ++j) { s[i][j] = __expf(s[i][j] - mn); rs += s[i][j]; }
            rs += __shfl_xor_sync(0xffffffffu, rs, 1);
            rs += __shfl_xor_sync(0xffffffffu, rs, 2);
            rs += __shfl_xor_sync(0xffffffffu, rs, 4);
            rs += __shfl_xor_sync(0xffffffffu, rs, 8);
            lrow[i] = lrow[i] * corr + rs;
            mrow[i] = mn;
            #pragma unroll
            for (int j = 0; j < 8; ++j) o[i][j] *= corr;
            float* pp = &Ps[(ty * 8 + i) * 128 + tx * 8];
            *(float4*)(pp)     = make_float4(s[i][0], s[i][1], s[i][2], s[i][3]);
            *(float4*)(pp + 4) = make_float4(s[i][4], s[i][5], s[i][6], s[i][7]);
        }
        __syncthreads();   // K reads done + P visible

        // Load V tile (plain layout) over K's buffer
        #pragma unroll
        for (int it = 0; it < 16; ++it) {
            const int idx = it * 256 + tid;
            const int row = idx >> 5, dv = idx & 31;
            KVs4[row * 32 + dv] =
                *(const float4*)(qkv + (bS + k0 + row) * EQ_ + voff + dv * 4);
        }
        __syncthreads();

        // O += P * V
        for (int k = 0; k < 128; ++k) {
            const float4 v0 = KVs4[k * 32 + tx * 2];
            const float4 v1 = KVs4[k * 32 + tx * 2 + 1];
            #pragma unroll
            for (int i = 0; i < 8; ++i) {
                const float p = Ps[(ty * 8 + i) * 128 + k];
                o[i][0] += p * v0.x; o[i][1] += p * v0.y;
                o[i][2] += p * v0.z; o[i][3] += p * v0.w;
                o[i][4] += p * v1.x; o[i][5] += p * v1.y;
                o[i][6] += p * v1.z; o[i][7] += p * v1.w;
            }
        }
    }

    // Epilogue: O / l -> attention output [b, s, h*128 + d]
    #pragma unroll
    for (int i = 0; i < 8; ++i) {
        const float inv = 1.0f / lrow[i];
        float* orow = outp + (bS + q0 + ty * 8 + i) * DM_ + (size_t)h * DH_ + tx * 8;
        *(float4*)(orow)     = make_float4(o[i][0]*inv, o[i][1]*inv, o[i][2]*inv, o[i][3]*inv);
        *(float4*)(orow + 4) = make_float4(o[i][4]*inv, o[i][5]*inv, o[i][6]*inv, o[i][7]*inv);
    }
}

// ---------------------------------------------------------------------------
// Launch: QKV projection -> flash attention -> output projection
// Inputs (metadata order): x, mask, Wqkv, Wo. Output: [B,S,2048] fp32.
// ---------------------------------------------------------------------------
extern "C" void kernel_launch(void* const* d_in, const int* in_sizes, int n_in,
                              void* d_out, int out_size)
{
    const float* x    = (const float*)d_in[0];
    const float* mask = (const float*)d_in[1];
    const float* Wqkv = (const float*)d_in[2];
    const float* Wo   = (const float*)d_in[3];
    float* out = (float*)d_out;

    float *qkv_p = nullptr, *att_p = nullptr;
    cudaGetSymbolAddress((void**)&qkv_p, g_qkv);
    cudaGetSymbolAddress((void**)&att_p, g_att);
    cudaFuncSetAttribute(flash_attn, cudaFuncAttributeMaxDynamicSharedMemorySize,
                         FLASH_SMEM);

    // qkv[ m=8192, e=3072 ] = x[8192,2048] @ Wqkv[3072,2048]^T
    gemm_nt<<<dim3(EQ_ / 128, MROWS_ / 128), 256>>>(x, Wqkv, qkv_p,
                                                    MROWS_, EQ_, DM_);
    // attention
    flash_attn<<<dim3(S_ / 128, HQ_, B_), 256, FLASH_SMEM>>>(qkv_p, mask, att_p);
    // out[8192,2048] = att[8192,2048] @ Wo[2048,2048]^T
    gemm_nt<<<dim3(DM_ / 128, MROWS_ / 128), 256>>>(att_p, Wo, out,
                                                    MROWS_, DM_, DM_);
}

// round 4
// speedup vs baseline: 1.2567x; 1.2567x over previous
#include <cuda_runtime.h>
#include <cuda_bf16.h>
#include <cstdint>
#include <cstddef>

// Problem constants
#define B_   4
#define S_   2048
#define DM_  2048
#define HQ_  16
#define DH_  128
#define EQ_  3072      // (H_Q + 2*H_KV) * D_HEAD
#define MR_  8192      // B*S

// ---------------------------------------------------------------------------
// Scratch (allocation-free rule: __device__ globals)
// ---------------------------------------------------------------------------
__device__ float g_qkv[(size_t)MR_ * EQ_];   // fused QKV output (fp32)
__device__ float g_att[(size_t)MR_ * DM_];   // attention output (fp32)
// bf16 hi/lo split planes
__device__ __nv_bfloat16 g_xh[(size_t)MR_ * DM_];
__device__ __nv_bfloat16 g_xl[(size_t)MR_ * DM_];
__device__ __nv_bfloat16 g_wqh[(size_t)EQ_ * DM_];
__device__ __nv_bfloat16 g_wql[(size_t)EQ_ * DM_];
__device__ __nv_bfloat16 g_ah[(size_t)MR_ * DM_];
__device__ __nv_bfloat16 g_al[(size_t)MR_ * DM_];
__device__ __nv_bfloat16 g_woh[(size_t)DM_ * DM_];
__device__ __nv_bfloat16 g_wol[(size_t)DM_ * DM_];

// ---------------------------------------------------------------------------
// warp-MMA helpers (base-target PTX: sm_80+, no 'a' features)
// ---------------------------------------------------------------------------
__device__ __forceinline__ uint32_t smem_u32(const void* p) {
    uint32_t a;
    asm("{ .reg .u64 t; cvta.to.shared.u64 t, %1; cvt.u32.u64 %0, t; }"
        : "=r"(a) : "l"(p));
    return a;
}

__device__ __forceinline__ void ldmx4(uint32_t& r0, uint32_t& r1,
                                      uint32_t& r2, uint32_t& r3, uint32_t a) {
    asm volatile("ldmatrix.sync.aligned.m8n8.x4.shared.b16 {%0,%1,%2,%3}, [%4];"
                 : "=r"(r0), "=r"(r1), "=r"(r2), "=r"(r3) : "r"(a));
}

__device__ __forceinline__ void mma16816(float* d, const uint32_t* a,
                                         const uint32_t* b) {
    asm volatile(
        "mma.sync.aligned.m16n8k16.row.col.f32.bf16.bf16.f32 "
        "{%0,%1,%2,%3}, {%4,%5,%6,%7}, {%8,%9}, {%0,%1,%2,%3};"
        : "+f"(d[0]), "+f"(d[1]), "+f"(d[2]), "+f"(d[3])
        : "r"(a[0]), "r"(a[1]), "r"(a[2]), "r"(a[3]), "r"(b[0]), "r"(b[1]));
}

// ---------------------------------------------------------------------------
// fp32 -> bf16 hi/lo split
// ---------------------------------------------------------------------------
__global__ void cvt_split(const float4* __restrict__ x,
                          __nv_bfloat162* __restrict__ hi,
                          __nv_bfloat162* __restrict__ lo, int n4)
{
    int i = blockIdx.x * blockDim.x + threadIdx.x;
    if (i >= n4) return;
    float4 v = x[i];
    __nv_bfloat16 h0 = __float2bfloat16(v.x), h1 = __float2bfloat16(v.y);
    __nv_bfloat16 h2 = __float2bfloat16(v.z), h3 = __float2bfloat16(v.w);
    __nv_bfloat16 l0 = __float2bfloat16(v.x - __bfloat162float(h0));
    __nv_bfloat16 l1 = __float2bfloat16(v.y - __bfloat162float(h1));
    __nv_bfloat16 l2 = __float2bfloat16(v.z - __bfloat162float(h2));
    __nv_bfloat16 l3 = __float2bfloat16(v.w - __bfloat162float(h3));
    hi[2*i]   = __nv_bfloat162(h0, h1);
    hi[2*i+1] = __nv_bfloat162(h2, h3);
    lo[2*i]   = __nv_bfloat162(l0, l1);
    lo[2*i+1] = __nv_bfloat162(l2, l3);
}

// ---------------------------------------------------------------------------
// 3xBF16 GEMM via mma.sync: C[M,N] = (Ah+Al)[M,K] * (Bh+Bl)[N,K]^T
// 128x128 CTA tile, 8 warps (2x4), 64x32 warp tile, K-chunk 32.
// smem planes padded to stride 40 bf16 (80B rows) -> conflict-free ldmatrix.
// ---------------------------------------------------------------------------
#define TSTRIDE 40   // bf16 elements per smem row (32 data + 8 pad)

__global__ void __launch_bounds__(256) gemm_bf3(
    const __nv_bfloat16* __restrict__ Ah, const __nv_bfloat16* __restrict__ Al,
    const __nv_bfloat16* __restrict__ Bh, const __nv_bfloat16* __restrict__ Bl,
    float* __restrict__ C, int M, int N, int K)
{
    __shared__ __nv_bfloat16 sAh[128 * TSTRIDE];
    __shared__ __nv_bfloat16 sAl[128 * TSTRIDE];
    __shared__ __nv_bfloat16 sBh[128 * TSTRIDE];
    __shared__ __nv_bfloat16 sBl[128 * TSTRIDE];

    const int tid  = threadIdx.x;
    const int wid  = tid >> 5;
    const int lane = tid & 31;
    const int wm   = wid >> 2;          // 0..1 -> rows wm*64..+63
    const int wn   = wid & 3;           // 0..3 -> cols wn*32..+31
    const int m0 = blockIdx.y << 7;
    const int n0 = blockIdx.x << 7;

    const __nv_bfloat16* pAh = Ah + (size_t)m0 * K;
    const __nv_bfloat16* pAl = Al + (size_t)m0 * K;
    const __nv_bfloat16* pBh = Bh + (size_t)n0 * K;
    const __nv_bfloat16* pBl = Bl + (size_t)n0 * K;

    // copy mapping: 512 16B-vectors per plane, 2 per thread
    const int row0 = (tid * 2) >> 2;        // rows: 4 vecs per row
    const int cv0  = (tid * 2) & 3;         // 16B col-vector within row
    // idx and idx+1 share the same row (cv0 in {0,2})

    float acc[4][4][4];
    #pragma unroll
    for (int i = 0; i < 4; ++i)
        #pragma unroll
        for (int j = 0; j < 4; ++j)
            #pragma unroll
            for (int q = 0; q < 4; ++q) acc[i][j][q] = 0.0f;

    // ldmatrix addresses (per-lane), within a plane
    const uint32_t bAh = smem_u32(sAh), bAl = smem_u32(sAl);
    const uint32_t bBh = smem_u32(sBh), bBl = smem_u32(sBl);
    const int a_row = wm * 64 + (lane & 15);
    const int a_kh  = (lane >> 4) * 8;                    // 0 / 8
    const int b_row = wn * 32 + (lane & 7) + ((lane >> 4) << 3);
    const int b_kh  = ((lane >> 3) & 1) * 8;

    const int NC = K >> 5;   // chunks of 32

    float4 pf[8];
    {   // prefetch chunk 0
        const size_t go0 = (size_t)row0 * K + cv0 * 8;
        const size_t go1 = (size_t)row0 * K + (cv0 + 1) * 8;
        pf[0] = *(const float4*)(pAh + go0); pf[1] = *(const float4*)(pAh + go1);
        pf[2] = *(const float4*)(pAl + go0); pf[3] = *(const float4*)(pAl + go1);
        pf[4] = *(const float4*)(pBh + go0); pf[5] = *(const float4*)(pBh + go1);
        pf[6] = *(const float4*)(pBl + go0); pf[7] = *(const float4*)(pBl + go1);
    }

    for (int c = 0; c < NC; ++c) {
        __syncthreads();   // previous chunk's readers done
        {
            const uint32_t so0 = row0 * (TSTRIDE * 2) + cv0 * 16;
            const uint32_t so1 = so0 + 16;
            *(float4*)((char*)sAh + so0) = pf[0]; *(float4*)((char*)sAh + so1) = pf[1];
            *(float4*)((char*)sAl + so0) = pf[2]; *(float4*)((char*)sAl + so1) = pf[3];
            *(float4*)((char*)sBh + so0) = pf[4]; *(float4*)((char*)sBh + so1) = pf[5];
            *(float4*)((char*)sBl + so0) = pf[6]; *(float4*)((char*)sBl + so1) = pf[7];
        }
        __syncthreads();

        if (c + 1 < NC) {   // issue next-chunk LDGs; consumed at next STS
            const size_t go0 = (size_t)row0 * K + (c + 1) * 32 + cv0 * 8;
            const size_t go1 = go0 + 8;
            pf[0] = *(const float4*)(pAh + go0); pf[1] = *(const float4*)(pAh + go1);
            pf[2] = *(const float4*)(pAl + go0); pf[3] = *(const float4*)(pAl + go1);
            pf[4] = *(const float4*)(pBh + go0); pf[5] = *(const float4*)(pBh + go1);
            pf[6] = *(const float4*)(pBl + go0); pf[7] = *(const float4*)(pBl + go1);
        }

        #pragma unroll
        for (int ks = 0; ks < 2; ++ks) {
            const int kk = ks * 16;
            // A fragments: 4 m16 blocks x {hi,lo}
            uint32_t fah[4][4], fal[4][4];
            #pragma unroll
            for (int mi = 0; mi < 4; ++mi) {
                const uint32_t off =
                    (uint32_t)(a_row + mi * 16) * (TSTRIDE * 2) + (kk + a_kh) * 2;
                ldmx4(fah[mi][0], fah[mi][1], fah[mi][2], fah[mi][3], bAh + off);
                ldmx4(fal[mi][0], fal[mi][1], fal[mi][2], fal[mi][3], bAl + off);
            }
            // B fragments: 2 n16 blocks -> 4 n8 frags x {hi,lo}
            uint32_t fbh[4][2], fbl[4][2];
            #pragma unroll
            for (int nb = 0; nb < 2; ++nb) {
                const uint32_t off =
                    (uint32_t)(b_row + nb * 16) * (TSTRIDE * 2) + (kk + b_kh) * 2;
                uint32_t r0, r1, r2, r3;
                ldmx4(r0, r1, r2, r3, bBh + off);
                fbh[nb*2][0] = r0; fbh[nb*2][1] = r1;
                fbh[nb*2+1][0] = r2; fbh[nb*2+1][1] = r3;
                ldmx4(r0, r1, r2, r3, bBl + off);
                fbl[nb*2][0] = r0; fbl[nb*2][1] = r1;
                fbl[nb*2+1][0] = r2; fbl[nb*2+1][1] = r3;
            }
            #pragma unroll
            for (int mi = 0; mi < 4; ++mi)
                #pragma unroll
                for (int nj = 0; nj < 4; ++nj) {
                    mma16816(acc[mi][nj], fah[mi], fbh[nj]);
                    mma16816(acc[mi][nj], fah[mi], fbl[nj]);
                    mma16816(acc[mi][nj], fal[mi], fbh[nj]);
                }
        }
    }

    // epilogue: fragment -> C
    #pragma unroll
    for (int mi = 0; mi < 4; ++mi) {
        const int r0 = m0 + wm * 64 + mi * 16 + (lane >> 2);
        #pragma unroll
        for (int nj = 0; nj < 4; ++nj) {
            const int ccol = n0 + wn * 32 + nj * 8 + (lane & 3) * 2;
            *(float2*)(C + (size_t)r0 * N + ccol) =
                make_float2(acc[mi][nj][0], acc[mi][nj][1]);
            *(float2*)(C + (size_t)(r0 + 8) * N + ccol) =
                make_float2(acc[mi][nj][2], acc[mi][nj][3]);
        }
    }
}

// ---------------------------------------------------------------------------
// Flash attention (unchanged from R1 — passing fp32 SIMT version)
// ---------------------------------------------------------------------------
#define FLASH_SMEM (3 * 128 * 128 * 4)

__global__ void __launch_bounds__(256, 1) flash_attn(
    const float* __restrict__ qkv, const float* __restrict__ mask,
    float* __restrict__ outp)
{
    extern __shared__ float sm[];
    float4* Qs4  = (float4*)sm;
    float4* KVs4 = (float4*)(sm + 128 * 128);
    float*  Ps   = sm + 2 * 128 * 128;

    const int tid = threadIdx.x;
    const int ty  = tid >> 4;
    const int tx  = tid & 15;
    const int q0  = blockIdx.x << 7;
    const int h   = blockIdx.y;
    const int b   = blockIdx.z;
    const int kh  = h >> 2;
    const size_t bS   = (size_t)b * S_;
    const size_t qoff = (size_t)h * DH_;
    const size_t koff = 2048 + (size_t)kh * DH_;
    const size_t voff = 2560 + (size_t)kh * DH_;
    const float scale = 0.08838834764831845f;

    #pragma unroll
    for (int it = 0; it < 16; ++it) {
        const int idx = it * 256 + tid;
        const int row = idx >> 5, dv = idx & 31;
        float4 q = *(const float4*)(qkv + (bS + q0 + row) * EQ_ + qoff + dv * 4);
        q.x *= scale; q.y *= scale; q.z *= scale; q.w *= scale;
        Qs4[row * 32 + dv] = q;
    }

    float o[8][8];
    #pragma unroll
    for (int i = 0; i < 8; ++i)
        #pragma unroll
        for (int j = 0; j < 8; ++j) o[i][j] = 0.0f;
    float mrow[8], lrow[8];
    #pragma unroll
    for (int i = 0; i < 8; ++i) { mrow[i] = -3.0e38f; lrow[i] = 0.0f; }

    for (int k0 = 0; k0 < S_; k0 += 128) {
        __syncthreads();
        #pragma unroll
        for (int it = 0; it < 16; ++it) {
            const int idx = it * 256 + tid;
            const int row = idx >> 5, dv = idx & 31;
            float4 kf = *(const float4*)(qkv + (bS + k0 + row) * EQ_ + koff + dv * 4);
            KVs4[row * 32 + (dv ^ (row & 7))] = kf;
        }
        __syncthreads();

        float s[8][8];
        #pragma unroll
        for (int i = 0; i < 8; ++i)
            #pragma unroll
            for (int j = 0; j < 8; ++j) s[i][j] = 0.0f;

        for (int dv = 0; dv < 32; ++dv) {
            float4 kf[8];
            #pragma unroll
            for (int j = 0; j < 8; ++j) {
                const int kc = tx * 8 + j;
                kf[j] = KVs4[kc * 32 + (dv ^ (kc & 7))];
            }
            #pragma unroll
            for (int i = 0; i < 8; ++i) {
                const float4 qf = Qs4[(ty * 8 + i) * 32 + dv];
                #pragma unroll
                for (int j = 0; j < 8; ++j) {
                    s[i][j] += qf.x * kf[j].x + qf.y * kf[j].y
                             + qf.z * kf[j].z + qf.w * kf[j].w;
                }
            }
        }

        #pragma unroll
        for (int i = 0; i < 8; ++i) {
            const float* mp = mask + (size_t)(q0 + ty * 8 + i) * S_ + k0 + tx * 8;
            const float4 m0v = *(const float4*)(mp);
            const float4 m1v = *(const float4*)(mp + 4);
            s[i][0] += m0v.x; s[i][1] += m0v.y; s[i][2] += m0v.z; s[i][3] += m0v.w;
            s[i][4] += m1v.x; s[i][5] += m1v.y; s[i][6] += m1v.z; s[i][7] += m1v.w;
        }

        #pragma unroll
        for (int i = 0; i < 8; ++i) {
            float rm = s[i][0];
            #pragma unroll
            for (int j = 1; j < 8; ++j) rm = fmaxf(rm, s[i][j]);
            rm = fmaxf(rm, __shfl_xor_sync(0xffffffffu, rm, 1));
            rm = fmaxf(rm, __shfl_xor_sync(0xffffffffu, rm, 2));
            rm = fmaxf(rm, __shfl_xor_sync(0xffffffffu, rm, 4));
            rm = fmaxf(rm, __shfl_xor_sync(0xffffffffu, rm, 8));
            const float mn   = fmaxf(mrow[i], rm);
            const float corr = __expf(mrow[i] - mn);
            float rs = 0.0f;
            #pragma unroll
            for (int j = 0; j < 8; ++j) { s[i][j] = __expf(s[i][j] - mn); rs += s[i][j]; }
            rs += __shfl_xor_sync(0xffffffffu, rs, 1);
            rs += __shfl_xor_sync(0xffffffffu, rs, 2);
            rs += __shfl_xor_sync(0xffffffffu, rs, 4);
            rs += __shfl_xor_sync(0xffffffffu, rs, 8);
            lrow[i] = lrow[i] * corr + rs;
            mrow[i] = mn;
            #pragma unroll
            for (int j = 0; j < 8; ++j) o[i][j] *= corr;
            float* pp = &Ps[(ty * 8 + i) * 128 + tx * 8];
            *(float4*)(pp)     = make_float4(s[i][0], s[i][1], s[i][2], s[i][3]);
            *(float4*)(pp + 4) = make_float4(s[i][4], s[i][5], s[i][6], s[i][7]);
        }
        __syncthreads();

        #pragma unroll
        for (int it = 0; it < 16; ++it) {
            const int idx = it * 256 + tid;
            const int row = idx >> 5, dv = idx & 31;
            KVs4[row * 32 + dv] =
                *(const float4*)(qkv + (bS + k0 + row) * EQ_ + voff + dv * 4);
        }
        __syncthreads();

        for (int k = 0; k < 128; ++k) {
            const float4 v0 = KVs4[k * 32 + tx * 2];
            const float4 v1 = KVs4[k * 32 + tx * 2 + 1];
            #pragma unroll
            for (int i = 0; i < 8; ++i) {
                const float p = Ps[(ty * 8 + i) * 128 + k];
                o[i][0] += p * v0.x; o[i][1] += p * v0.y;
                o[i][2] += p * v0.z; o[i][3] += p * v0.w;
                o[i][4] += p * v1.x; o[i][5] += p * v1.y;
                o[i][6] += p * v1.z; o[i][7] += p * v1.w;
            }
        }
    }

    #pragma unroll
    for (int i = 0; i < 8; ++i) {
        const float inv = 1.0f / lrow[i];
        float* orow = outp + (bS + q0 + ty * 8 + i) * DM_ + (size_t)h * DH_ + tx * 8;
        *(float4*)(orow)     = make_float4(o[i][0]*inv, o[i][1]*inv, o[i][2]*inv, o[i][3]*inv);
        *(float4*)(orow + 4) = make_float4(o[i][4]*inv, o[i][5]*inv, o[i][6]*inv, o[i][7]*inv);
    }
}

// ---------------------------------------------------------------------------
// Launch
// ---------------------------------------------------------------------------
extern "C" void kernel_launch(void* const* d_in, const int* in_sizes, int n_in,
                              void* d_out, int out_size)
{
    const float* x    = (const float*)d_in[0];
    const float* mask = (const float*)d_in[1];
    const float* Wqkv = (const float*)d_in[2];
    const float* Wo   = (const float*)d_in[3];
    float* out = (float*)d_out;

    float *qkv_p, *att_p;
    __nv_bfloat16 *xh, *xl, *wqh, *wql, *ah, *al, *woh, *wol;
    cudaGetSymbolAddress((void**)&qkv_p, g_qkv);
    cudaGetSymbolAddress((void**)&att_p, g_att);
    cudaGetSymbolAddress((void**)&xh,  g_xh);
    cudaGetSymbolAddress((void**)&xl,  g_xl);
    cudaGetSymbolAddress((void**)&wqh, g_wqh);
    cudaGetSymbolAddress((void**)&wql, g_wql);
    cudaGetSymbolAddress((void**)&ah,  g_ah);
    cudaGetSymbolAddress((void**)&al,  g_al);
    cudaGetSymbolAddress((void**)&woh, g_woh);
    cudaGetSymbolAddress((void**)&wol, g_wol);

    cudaFuncSetAttribute(flash_attn, cudaFuncAttributeMaxDynamicSharedMemorySize,
                         FLASH_SMEM);

    // split inputs to bf16 hi/lo
    {
        int n4 = (MR_ * DM_) / 4;
        cvt_split<<<(n4 + 255) / 256, 256>>>((const float4*)x,
            (__nv_bfloat162*)xh, (__nv_bfloat162*)xl, n4);
        n4 = (EQ_ * DM_) / 4;
        cvt_split<<<(n4 + 255) / 256, 256>>>((const float4*)Wqkv,
            (__nv_bfloat162*)wqh, (__nv_bfloat162*)wql, n4);
        n4 = (DM_ * DM_) / 4;
        cvt_split<<<(n4 + 255) / 256, 256>>>((const float4*)Wo,
            (__nv_bfloat162*)woh, (__nv_bfloat162*)wol, n4);
    }

    // qkv = x @ Wqkv^T  (3xBF16 mma.sync)
    gemm_bf3<<<dim3(EQ_ / 128, MR_ / 128), 256>>>(
        xh, xl, wqh, wql, qkv_p, MR_, EQ_, DM_);

    // attention (fp32 SIMT)
    flash_attn<<<dim3(S_ / 128, HQ_, B_), 256, FLASH_SMEM>>>(qkv_p, mask, att_p);

    // split attention output
    {
        int n4 = (MR_ * DM_) / 4;
        cvt_split<<<(n4 + 255) / 256, 256>>>((const float4*)att_p,
            (__nv_bfloat162*)ah, (__nv_bfloat162*)al, n4);
    }

    // out = att @ Wo^T  (3xBF16 mma.sync)
    gemm_bf3<<<dim3(DM_ / 128, MR_ / 128), 256>>>(
        ah, al, woh, wol, out, MR_, DM_, DM_);
}

// round 7
// speedup vs baseline: 3.7976x; 3.0219x over previous
#include <cuda_runtime.h>
#include <cuda_bf16.h>
#include <cstdint>
#include <cstddef>

// Problem constants
#define B_   4
#define S_   2048
#define DM_  2048
#define HQ_  16
#define DH_  128
#define EQ_  3072      // (H_Q + 2*H_KV) * D_HEAD
#define MR_  8192      // B*S

// ---------------------------------------------------------------------------
// Scratch (allocation-free rule: __device__ globals)
// ---------------------------------------------------------------------------
__device__ float g_qkv[(size_t)MR_ * EQ_];   // fused QKV output (fp32)
__device__ float g_att[(size_t)MR_ * DM_];   // attention output (fp32)
// bf16 hi/lo split planes
__device__ __nv_bfloat16 g_xh[(size_t)MR_ * DM_];
__device__ __nv_bfloat16 g_xl[(size_t)MR_ * DM_];
__device__ __nv_bfloat16 g_wqh[(size_t)EQ_ * DM_];
__device__ __nv_bfloat16 g_wql[(size_t)EQ_ * DM_];
__device__ __nv_bfloat16 g_ah[(size_t)MR_ * DM_];
__device__ __nv_bfloat16 g_al[(size_t)MR_ * DM_];
__device__ __nv_bfloat16 g_woh[(size_t)DM_ * DM_];
__device__ __nv_bfloat16 g_wol[(size_t)DM_ * DM_];

// ---------------------------------------------------------------------------
// warp-MMA helpers (base-target PTX: sm_80+, no 'a' features)
// ---------------------------------------------------------------------------
__device__ __forceinline__ uint32_t smem_u32(const void* p) {
    uint32_t a;
    asm("{ .reg .u64 t; cvta.to.shared.u64 t, %1; cvt.u32.u64 %0, t; }"
        : "=r"(a) : "l"(p));
    return a;
}

__device__ __forceinline__ void ldmx4(uint32_t& r0, uint32_t& r1,
                                      uint32_t& r2, uint32_t& r3, uint32_t a) {
    asm volatile("ldmatrix.sync.aligned.m8n8.x4.shared.b16 {%0,%1,%2,%3}, [%4];"
                 : "=r"(r0), "=r"(r1), "=r"(r2), "=r"(r3) : "r"(a));
}

__device__ __forceinline__ void ldmx4t(uint32_t& r0, uint32_t& r1,
                                       uint32_t& r2, uint32_t& r3, uint32_t a) {
    asm volatile("ldmatrix.sync.aligned.m8n8.x4.trans.shared.b16 {%0,%1,%2,%3}, [%4];"
                 : "=r"(r0), "=r"(r1), "=r"(r2), "=r"(r3) : "r"(a));
}

__device__ __forceinline__ void mma16816(float* d, const uint32_t* a,
                                         const uint32_t* b) {
    asm volatile(
        "mma.sync.aligned.m16n8k16.row.col.f32.bf16.bf16.f32 "
        "{%0,%1,%2,%3}, {%4,%5,%6,%7}, {%8,%9}, {%0,%1,%2,%3};"
        : "+f"(d[0]), "+f"(d[1]), "+f"(d[2]), "+f"(d[3])
        : "r"(a[0]), "r"(a[1]), "r"(a[2]), "r"(a[3]), "r"(b[0]), "r"(b[1]));
}

// pack two fp32 -> bf16x2 (round-nearest)
__device__ __forceinline__ uint32_t packbf(float a, float b) {
    __nv_bfloat162 t = __float22bfloat162_rn(make_float2(a, b));
    return *reinterpret_cast<uint32_t*>(&t);
}
__device__ __forceinline__ float bflo(uint32_t p) {
    __nv_bfloat162 t = *reinterpret_cast<__nv_bfloat162*>(&p);
    return __bfloat162float(t.x);
}
__device__ __forceinline__ float bfhi(uint32_t p) {
    __nv_bfloat162 t = *reinterpret_cast<__nv_bfloat162*>(&p);
    return __bfloat162float(t.y);
}

// fp32x4 -> hi/lo bf16x2 pairs (packed as uint2 for 8B smem stores)
__device__ __forceinline__ void split4(float4 v, uint2& h, uint2& l) {
    uint32_t h0 = packbf(v.x, v.y), h1 = packbf(v.z, v.w);
    uint32_t l0 = packbf(v.x - bflo(h0), v.y - bfhi(h0));
    uint32_t l1 = packbf(v.z - bflo(h1), v.w - bfhi(h1));
    h = make_uint2(h0, h1);
    l = make_uint2(l0, l1);
}

// ---------------------------------------------------------------------------
// fp32 -> bf16 hi/lo split (global)
// ---------------------------------------------------------------------------
__global__ void cvt_split(const float4* __restrict__ x,
                          __nv_bfloat162* __restrict__ hi,
                          __nv_bfloat162* __restrict__ lo, int n4)
{
    int i = blockIdx.x * blockDim.x + threadIdx.x;
    if (i >= n4) return;
    float4 v = x[i];
    uint2 h, l;
    split4(v, h, l);
    *reinterpret_cast<uint2*>(hi + 2 * (size_t)i) = h;
    *reinterpret_cast<uint2*>(lo + 2 * (size_t)i) = l;
}

// ---------------------------------------------------------------------------
// 3xBF16 GEMM via mma.sync (unchanged from R4 passing version)
// ---------------------------------------------------------------------------
#define TSTRIDE 40

__global__ void __launch_bounds__(256) gemm_bf3(
    const __nv_bfloat16* __restrict__ Ah, const __nv_bfloat16* __restrict__ Al,
    const __nv_bfloat16* __restrict__ Bh, const __nv_bfloat16* __restrict__ Bl,
    float* __restrict__ C, int M, int N, int K)
{
    __shared__ __nv_bfloat16 sAh[128 * TSTRIDE];
    __shared__ __nv_bfloat16 sAl[128 * TSTRIDE];
    __shared__ __nv_bfloat16 sBh[128 * TSTRIDE];
    __shared__ __nv_bfloat16 sBl[128 * TSTRIDE];

    const int tid  = threadIdx.x;
    const int wid  = tid >> 5;
    const int lane = tid & 31;
    const int wm   = wid >> 2;
    const int wn   = wid & 3;
    const int m0 = blockIdx.y << 7;
    const int n0 = blockIdx.x << 7;

    const __nv_bfloat16* pAh = Ah + (size_t)m0 * K;
    const __nv_bfloat16* pAl = Al + (size_t)m0 * K;
    const __nv_bfloat16* pBh = Bh + (size_t)n0 * K;
    const __nv_bfloat16* pBl = Bl + (size_t)n0 * K;

    const int row0 = (tid * 2) >> 2;
    const int cv0  = (tid * 2) & 3;

    float acc[4][4][4];
    #pragma unroll
    for (int i = 0; i < 4; ++i)
        #pragma unroll
        for (int j = 0; j < 4; ++j)
            #pragma unroll
            for (int q = 0; q < 4; ++q) acc[i][j][q] = 0.0f;

    const uint32_t bAh = smem_u32(sAh), bAl = smem_u32(sAl);
    const uint32_t bBh = smem_u32(sBh), bBl = smem_u32(sBl);
    const int a_row = wm * 64 + (lane & 15);
    const int a_kh  = (lane >> 4) * 8;
    const int b_row = wn * 32 + (lane & 7) + ((lane >> 4) << 3);
    const int b_kh  = ((lane >> 3) & 1) * 8;

    const int NC = K >> 5;

    float4 pf[8];
    {
        const size_t go0 = (size_t)row0 * K + cv0 * 8;
        const size_t go1 = (size_t)row0 * K + (cv0 + 1) * 8;
        pf[0] = *(const float4*)(pAh + go0); pf[1] = *(const float4*)(pAh + go1);
        pf[2] = *(const float4*)(pAl + go0); pf[3] = *(const float4*)(pAl + go1);
        pf[4] = *(const float4*)(pBh + go0); pf[5] = *(const float4*)(pBh + go1);
        pf[6] = *(const float4*)(pBl + go0); pf[7] = *(const float4*)(pBl + go1);
    }

    for (int c = 0; c < NC; ++c) {
        __syncthreads();
        {
            const uint32_t so0 = row0 * (TSTRIDE * 2) + cv0 * 16;
            const uint32_t so1 = so0 + 16;
            *(float4*)((char*)sAh + so0) = pf[0]; *(float4*)((char*)sAh + so1) = pf[1];
            *(float4*)((char*)sAl + so0) = pf[2]; *(float4*)((char*)sAl + so1) = pf[3];
            *(float4*)((char*)sBh + so0) = pf[4]; *(float4*)((char*)sBh + so1) = pf[5];
            *(float4*)((char*)sBl + so0) = pf[6]; *(float4*)((char*)sBl + so1) = pf[7];
        }
        __syncthreads();

        if (c + 1 < NC) {
            const size_t go0 = (size_t)row0 * K + (c + 1) * 32 + cv0 * 8;
            const size_t go1 = go0 + 8;
            pf[0] = *(const float4*)(pAh + go0); pf[1] = *(const float4*)(pAh + go1);
            pf[2] = *(const float4*)(pAl + go0); pf[3] = *(const float4*)(pAl + go1);
            pf[4] = *(const float4*)(pBh + go0); pf[5] = *(const float4*)(pBh + go1);
            pf[6] = *(const float4*)(pBl + go0); pf[7] = *(const float4*)(pBl + go1);
        }

        #pragma unroll
        for (int ks = 0; ks < 2; ++ks) {
            const int kk = ks * 16;
            uint32_t fah[4][4], fal[4][4];
            #pragma unroll
            for (int mi = 0; mi < 4; ++mi) {
                const uint32_t off =
                    (uint32_t)(a_row + mi * 16) * (TSTRIDE * 2) + (kk + a_kh) * 2;
                ldmx4(fah[mi][0], fah[mi][1], fah[mi][2], fah[mi][3], bAh + off);
                ldmx4(fal[mi][0], fal[mi][1], fal[mi][2], fal[mi][3], bAl + off);
            }
            uint32_t fbh[4][2], fbl[4][2];
            #pragma unroll
            for (int nb = 0; nb < 2; ++nb) {
                const uint32_t off =
                    (uint32_t)(b_row + nb * 16) * (TSTRIDE * 2) + (kk + b_kh) * 2;
                uint32_t r0, r1, r2, r3;
                ldmx4(r0, r1, r2, r3, bBh + off);
                fbh[nb*2][0] = r0; fbh[nb*2][1] = r1;
                fbh[nb*2+1][0] = r2; fbh[nb*2+1][1] = r3;
                ldmx4(r0, r1, r2, r3, bBl + off);
                fbl[nb*2][0] = r0; fbl[nb*2][1] = r1;
                fbl[nb*2+1][0] = r2; fbl[nb*2+1][1] = r3;
            }
            #pragma unroll
            for (int mi = 0; mi < 4; ++mi)
                #pragma unroll
                for (int nj = 0; nj < 4; ++nj) {
                    mma16816(acc[mi][nj], fah[mi], fbh[nj]);
                    mma16816(acc[mi][nj], fah[mi], fbl[nj]);
                    mma16816(acc[mi][nj], fal[mi], fbh[nj]);
                }
        }
    }

    #pragma unroll
    for (int mi = 0; mi < 4; ++mi) {
        const int r0 = m0 + wm * 64 + mi * 16 + (lane >> 2);
        #pragma unroll
        for (int nj = 0; nj < 4; ++nj) {
            const int ccol = n0 + wn * 32 + nj * 8 + (lane & 3) * 2;
            *(float2*)(C + (size_t)r0 * N + ccol) =
                make_float2(acc[mi][nj][0], acc[mi][nj][1]);
            *(float2*)(C + (size_t)(r0 + 8) * N + ccol) =
                make_float2(acc[mi][nj][2], acc[mi][nj][3]);
        }
    }
}

// ---------------------------------------------------------------------------
// Flash attention via mma.sync, 3xBF16 hi/lo for QK^T and P*V.
// 8 warps x 16 q-rows; 128 q-tile x 128 kv-tile, D=128.
// smem planes (bf16, row stride 136): Qh | Ql | KVh | KVl  (K then V reuse).
// ---------------------------------------------------------------------------
#define ASTRIDE   136                     // bf16 per smem row (128 + 8 pad)
#define PLANE_B   (128 * ASTRIDE * 2)     // 34816 bytes
#define OFF_QH    0
#define OFF_QL    (PLANE_B)
#define OFF_KVH   (2 * PLANE_B)
#define OFF_KVL   (3 * PLANE_B)
#define FLASH_SMEM (4 * PLANE_B)          // 139264

__global__ void __launch_bounds__(256, 1) flash_attn_mma(
    const float* __restrict__ qkv, const float* __restrict__ mask,
    float* __restrict__ outp)
{
    extern __shared__ char smem[];
    const uint32_t sb = smem_u32(smem);

    const int tid  = threadIdx.x;
    const int wid  = tid >> 5;
    const int lane = tid & 31;
    const int q0 = blockIdx.x << 7;
    const int h  = blockIdx.y;
    const int b  = blockIdx.z;
    const int kh = h >> 2;                       // GQA repeat_interleave(4)
    const size_t bS   = (size_t)b * S_;
    const size_t qoff = (size_t)h * DH_;
    const size_t koff = 2048 + (size_t)kh * DH_;
    const size_t voff = 2560 + (size_t)kh * DH_;
    const float scale = 0.08838834764831845f;    // 1/sqrt(128)

    // tile-fill mapping: idx -> (row, 4-float chunk)
    // each warp fills one row per iteration: conflict-free 8B stores
    // Q tile (pre-scaled) -> Qh/Ql
    #pragma unroll
    for (int it = 0; it < 16; ++it) {
        const int idx = it * 256 + tid;
        const int row = idx >> 5, dv = idx & 31;
        float4 v = *(const float4*)(qkv + (bS + q0 + row) * EQ_ + qoff + dv * 4);
        v.x *= scale; v.y *= scale; v.z *= scale; v.w *= scale;
        uint2 hh, ll;
        split4(v, hh, ll);
        const uint32_t so = row * (ASTRIDE * 2) + dv * 8;
        *(uint2*)(smem + OFF_QH + so) = hh;
        *(uint2*)(smem + OFF_QL + so) = ll;
    }

    // fragment row/col lane decomposition
    const int rql = lane >> 2;           // row_lo within 16-block
    const int cq2 = (lane & 3) * 2;      // col pair base within n8 block
    // ldmatrix lane addressing
    const int lm_row = lane & 15;                         // A-frag rows
    const int lm_kh  = (lane >> 4) * 8;                   // A-frag k half
    const int lb_row = (lane & 7) + ((lane >> 4) << 3);   // B-frag n row
    const int lb_kh  = ((lane >> 3) & 1) * 8;             // B-frag k half
    // V trans addressing
    const int lv_k = (lane & 7) + ((lane >> 3) & 1) * 8;  // k row within 16
    const int lv_n = (lane >> 4) * 8;                     // n col half

    float acc_o[16][4];
    #pragma unroll
    for (int nb = 0; nb < 16; ++nb)
        #pragma unroll
        for (int q = 0; q < 4; ++q) acc_o[nb][q] = 0.0f;
    float m_lo = -1.0e30f, m_hi = -1.0e30f, l_lo = 0.0f, l_hi = 0.0f;

    for (int k0 = 0; k0 < S_; k0 += 128) {
        __syncthreads();   // Q ready (iter0) / prior PV reads of KV done
        // ---- load K tile -> KVh/KVl ----
        #pragma unroll
        for (int it = 0; it < 16; ++it) {
            const int idx = it * 256 + tid;
            const int row = idx >> 5, dv = idx & 31;
            float4 v = *(const float4*)(qkv + (bS + k0 + row) * EQ_ + koff + dv * 4);
            uint2 hh, ll;
            split4(v, hh, ll);
            const uint32_t so = row * (ASTRIDE * 2) + dv * 8;
            *(uint2*)(smem + OFF_KVH + so) = hh;
            *(uint2*)(smem + OFF_KVL + so) = ll;
        }
        __syncthreads();

        // ---- S = Q K^T (3xBF16) ----
        float s[16][4];
        #pragma unroll
        for (int nb = 0; nb < 16; ++nb)
            #pragma unroll
            for (int q = 0; q < 4; ++q) s[nb][q] = 0.0f;

        #pragma unroll
        for (int kc = 0; kc < 8; ++kc) {
            uint32_t qh[4], ql[4];
            {
                const uint32_t off = (uint32_t)(wid * 16 + lm_row) * (ASTRIDE * 2)
                                   + (kc * 16 + lm_kh) * 2;
                ldmx4(qh[0], qh[1], qh[2], qh[3], sb + OFF_QH + off);
                ldmx4(ql[0], ql[1], ql[2], ql[3], sb + OFF_QL + off);
            }
            #pragma unroll
            for (int nb = 0; nb < 8; ++nb) {
                const uint32_t off = (uint32_t)(nb * 16 + lb_row) * (ASTRIDE * 2)
                                   + (kc * 16 + lb_kh) * 2;
                uint32_t kh0[2], kh1[2], kl0[2], kl1[2];
                {
                    uint32_t r0, r1, r2, r3;
                    ldmx4(r0, r1, r2, r3, sb + OFF_KVH + off);
                    kh0[0] = r0; kh0[1] = r1; kh1[0] = r2; kh1[1] = r3;
                    ldmx4(r0, r1, r2, r3, sb + OFF_KVL + off);
                    kl0[0] = r0; kl0[1] = r1; kl1[0] = r2; kl1[1] = r3;
                }
                mma16816(s[nb*2],   qh, kh0);
                mma16816(s[nb*2],   qh, kl0);
                mma16816(s[nb*2],   ql, kh0);
                mma16816(s[nb*2+1], qh, kh1);
                mma16816(s[nb*2+1], qh, kl1);
                mma16816(s[nb*2+1], ql, kh1);
            }
        }

        // ---- + mask ----
        {
            const int qrow_lo = q0 + wid * 16 + rql;
            #pragma unroll
            for (int nb = 0; nb < 16; ++nb) {
                const size_t mo = (size_t)qrow_lo * S_ + k0 + nb * 8 + cq2;
                const float2 mlo = *(const float2*)(mask + mo);
                const float2 mhi = *(const float2*)(mask + mo + 8 * S_);
                s[nb][0] += mlo.x; s[nb][1] += mlo.y;
                s[nb][2] += mhi.x; s[nb][3] += mhi.y;
            }
        }

        // ---- online softmax (rows r_lo, r_hi live in the 4-lane quad) ----
        {
            float mx0 = -1.0e30f, mx1 = -1.0e30f;
            #pragma unroll
            for (int nb = 0; nb < 16; ++nb) {
                mx0 = fmaxf(mx0, fmaxf(s[nb][0], s[nb][1]));
                mx1 = fmaxf(mx1, fmaxf(s[nb][2], s[nb][3]));
            }
            mx0 = fmaxf(mx0, __shfl_xor_sync(0xffffffffu, mx0, 1));
            mx0 = fmaxf(mx0, __shfl_xor_sync(0xffffffffu, mx0, 2));
            mx1 = fmaxf(mx1, __shfl_xor_sync(0xffffffffu, mx1, 1));
            mx1 = fmaxf(mx1, __shfl_xor_sync(0xffffffffu, mx1, 2));
            const float mn0 = fmaxf(m_lo, mx0), mn1 = fmaxf(m_hi, mx1);
            const float c0 = __expf(m_lo - mn0), c1 = __expf(m_hi - mn1);
            float sum0 = 0.0f, sum1 = 0.0f;
            #pragma unroll
            for (int nb = 0; nb < 16; ++nb) {
                s[nb][0] = __expf(s[nb][0] - mn0);
                s[nb][1] = __expf(s[nb][1] - mn0);
                s[nb][2] = __expf(s[nb][2] - mn1);
                s[nb][3] = __expf(s[nb][3] - mn1);
                sum0 += s[nb][0] + s[nb][1];
                sum1 += s[nb][2] + s[nb][3];
            }
            sum0 += __shfl_xor_sync(0xffffffffu, sum0, 1);
            sum0 += __shfl_xor_sync(0xffffffffu, sum0, 2);
            sum1 += __shfl_xor_sync(0xffffffffu, sum1, 1);
            sum1 += __shfl_xor_sync(0xffffffffu, sum1, 2);
            l_lo = l_lo * c0 + sum0;
            l_hi = l_hi * c1 + sum1;
            m_lo = mn0; m_hi = mn1;
            #pragma unroll
            for (int nb = 0; nb < 16; ++nb) {
                acc_o[nb][0] *= c0; acc_o[nb][1] *= c0;
                acc_o[nb][2] *= c1; acc_o[nb][3] *= c1;
            }
        }

        __syncthreads();   // all warps done reading K planes
        // ---- load V tile -> KVh/KVl ----
        #pragma unroll
        for (int it = 0; it < 16; ++it) {
            const int idx = it * 256 + tid;
            const int row = idx >> 5, dv = idx & 31;
            float4 v = *(const float4*)(qkv + (bS + k0 + row) * EQ_ + voff + dv * 4);
            uint2 hh, ll;
            split4(v, hh, ll);
            const uint32_t so = row * (ASTRIDE * 2) + dv * 8;
            *(uint2*)(smem + OFF_KVH + so) = hh;
            *(uint2*)(smem + OFF_KVL + so) = ll;
        }
        __syncthreads();

        // ---- O += P V (3xBF16; P from score frags via C->A layout identity) ----
        #pragma unroll
        for (int kc = 0; kc < 8; ++kc) {
            uint32_t ph[4], pl[4];
            {
                const float p0 = s[kc*2][0],   p1 = s[kc*2][1];
                const float p2 = s[kc*2][2],   p3 = s[kc*2][3];
                const float p4 = s[kc*2+1][0], p5 = s[kc*2+1][1];
                const float p6 = s[kc*2+1][2], p7 = s[kc*2+1][3];
                ph[0] = packbf(p0, p1); ph[1] = packbf(p2, p3);
                ph[2] = packbf(p4, p5); ph[3] = packbf(p6, p7);
                pl[0] = packbf(p0 - bflo(ph[0]), p1 - bfhi(ph[0]));
                pl[1] = packbf(p2 - bflo(ph[1]), p3 - bfhi(ph[1]));
                pl[2] = packbf(p4 - bflo(ph[2]), p5 - bfhi(ph[2]));
                pl[3] = packbf(p6 - bflo(ph[3]), p7 - bfhi(ph[3]));
            }
            #pragma unroll
            for (int nb = 0; nb < 8; ++nb) {
                const uint32_t off = (uint32_t)(kc * 16 + lv_k) * (ASTRIDE * 2)
                                   + (nb * 16 + lv_n) * 2;
                uint32_t vh0[2], vh1[2], vl0[2], vl1[2];
                {
                    uint32_t r0, r1, r2, r3;
                    ldmx4t(r0, r1, r2, r3, sb + OFF_KVH + off);
                    vh0[0] = r0; vh0[1] = r1; vh1[0] = r2; vh1[1] = r3;
                    ldmx4t(r0, r1, r2, r3, sb + OFF_KVL + off);
                    vl0[0] = r0; vl0[1] = r1; vl1[0] = r2; vl1[1] = r3;
                }
                mma16816(acc_o[nb*2],   ph, vh0);
                mma16816(acc_o[nb*2],   ph, vl0);
                mma16816(acc_o[nb*2],   pl, vh0);
                mma16816(acc_o[nb*2+1], ph, vh1);
                mma16816(acc_o[nb*2+1], ph, vl1);
                mma16816(acc_o[nb*2+1], pl, vh1);
            }
        }
    }

    // ---- epilogue: O / l -> [b, q, h*128 + d] ----
    {
        const float inv0 = 1.0f / l_lo, inv1 = 1.0f / l_hi;
        const int qrow_lo = q0 + wid * 16 + rql;
        float* orow0 = outp + (bS + qrow_lo) * DM_ + (size_t)h * DH_;
        float* orow1 = orow0 + (size_t)8 * DM_;
        #pragma unroll
        for (int nb = 0; nb < 16; ++nb) {
            const int dc = nb * 8 + cq2;
            *(float2*)(orow0 + dc) = make_float2(acc_o[nb][0] * inv0,
                                                 acc_o[nb][1] * inv0);
            *(float2*)(orow1 + dc) = make_float2(acc_o[nb][2] * inv1,
                                                 acc_o[nb][3] * inv1);
        }
    }
}

// ---------------------------------------------------------------------------
// Launch
// ---------------------------------------------------------------------------
extern "C" void kernel_launch(void* const* d_in, const int* in_sizes, int n_in,
                              void* d_out, int out_size)
{
    const float* x    = (const float*)d_in[0];
    const float* mask = (const float*)d_in[1];
    const float* Wqkv = (const float*)d_in[2];
    const float* Wo   = (const float*)d_in[3];
    float* out = (float*)d_out;

    float *qkv_p, *att_p;
    __nv_bfloat16 *xh, *xl, *wqh, *wql, *ah, *al, *woh, *wol;
    cudaGetSymbolAddress((void**)&qkv_p, g_qkv);
    cudaGetSymbolAddress((void**)&att_p, g_att);
    cudaGetSymbolAddress((void**)&xh,  g_xh);
    cudaGetSymbolAddress((void**)&xl,  g_xl);
    cudaGetSymbolAddress((void**)&wqh, g_wqh);
    cudaGetSymbolAddress((void**)&wql, g_wql);
    cudaGetSymbolAddress((void**)&ah,  g_ah);
    cudaGetSymbolAddress((void**)&al,  g_al);
    cudaGetSymbolAddress((void**)&woh, g_woh);
    cudaGetSymbolAddress((void**)&wol, g_wol);

    cudaFuncSetAttribute(flash_attn_mma,
                         cudaFuncAttributeMaxDynamicSharedMemorySize, FLASH_SMEM);

    // split inputs to bf16 hi/lo
    {
        int n4 = (MR_ * DM_) / 4;
        cvt_split<<<(n4 + 255) / 256, 256>>>((const float4*)x,
            (__nv_bfloat162*)xh, (__nv_bfloat162*)xl, n4);
        n4 = (EQ_ * DM_) / 4;
        cvt_split<<<(n4 + 255) / 256, 256>>>((const float4*)Wqkv,
            (__nv_bfloat162*)wqh, (__nv_bfloat162*)wql, n4);
        n4 = (DM_ * DM_) / 4;
        cvt_split<<<(n4 + 255) / 256, 256>>>((const float4*)Wo,
            (__nv_bfloat162*)woh, (__nv_bfloat162*)wol, n4);
    }

    // qkv = x @ Wqkv^T
    gemm_bf3<<<dim3(EQ_ / 128, MR_ / 128), 256>>>(
        xh, xl, wqh, wql, qkv_p, MR_, EQ_, DM_);

    // attention (3xBF16 mma.sync flash)
    flash_attn_mma<<<dim3(S_ / 128, HQ_, B_), 256, FLASH_SMEM>>>(
        qkv_p, mask, att_p);

    // split attention output
    {
        int n4 = (MR_ * DM_) / 4;
        cvt_split<<<(n4 + 255) / 256, 256>>>((const float4*)att_p,
            (__nv_bfloat162*)ah, (__nv_bfloat162*)al, n4);
    }

    // out = att @ Wo^T
    gemm_bf3<<<dim3(DM_ / 128, MR_ / 128), 256>>>(
        ah, al, woh, wol, out, MR_, DM_, DM_);
}